// round 7
// baseline (speedup 1.0000x reference)
#include <cuda_runtime.h>
#include <math.h>

#define Bb 8
#define Hh 32
#define Ff 8
#define Xx 128
#define Tt 256
#define Tm1 255

// ---------------- scratch (static device arrays; no allocations) ----------------
__device__ float  g_Gu[Bb*Xx*Hh*Ff];          // [b][x][i][f]
__device__ float  g_dHu[Bb*Hh*Xx*Tm1];        // [b][i][x][t]
__device__ float2 g_dXft[Xx*Bb*Tm1*Hh];       // [k][b][t][i]
__device__ float2 g_z0ft[Xx*Bb*Hh];           // [k][b][i]
__device__ float2 g_Zall[Xx*Bb*Tt*Hh];        // [k][b][t][i]
__device__ float2 g_Sfwd[Xx*Xx];              // [x][k]  shifted forward DFT
__device__ float2 g_Sinv[Xx*Xx];              // [k][x]  (real-part inverse, scaled)

// ---------------- packed f32x2 helpers (sm_103a) ----------------
__device__ __forceinline__ unsigned long long pk2(float lo, float hi) {
    unsigned long long r;
    asm("mov.b64 %0, {%1, %2};" : "=l"(r) : "f"(lo), "f"(hi));
    return r;
}
__device__ __forceinline__ void upk2(unsigned long long v, float& lo, float& hi) {
    asm("mov.b64 {%0, %1}, %2;" : "=f"(lo), "=f"(hi) : "l"(v));
}
__device__ __forceinline__ unsigned long long fma2(unsigned long long a,
                                                   unsigned long long b,
                                                   unsigned long long c) {
    unsigned long long d;
    asm("fma.rn.f32x2 %0, %1, %2, %3;" : "=l"(d) : "l"(a), "l"(b), "l"(c));
    return d;
}

// ---------------- K0: twiddle tables ----------------
__global__ void k0_tables() {
    int idx = blockIdx.x * blockDim.x + threadIdx.x;
    if (idx >= Xx * Xx) return;
    int k = idx >> 7, x = idx & 127;
    // forward: fftshift(fft(.)) -> S[k,x] = e^{-2*pi*i*(k+64)*x/128}
    int m = ((k + 64) * x) & 127;
    float a = -6.2831853071795864769f * (float)m / 128.0f;
    g_Sfwd[x * Xx + k] = make_float2(cosf(a), sinf(a));
    // inverse: out[x] = (1/128)(-1)^x sum_k (zr*cos(2pi kx/128) - zi*sin(2pi kx/128))
    int m2 = (k * x) & 127;
    float a2 = 6.2831853071795864769f * (float)m2 / 128.0f;
    float sc = ((x & 1) ? -1.0f : 1.0f) / 128.0f;
    g_Sinv[k * Xx + x] = make_float2(sc * cosf(a2), -sc * sinf(a2));
}

// ---------------- K1: Gu[b,x,i,f] = sum_h Gw[i,f,h] * z0[b,h,x] ----------------
__global__ void k1_gu(const float* __restrict__ z0, const float* __restrict__ Gw) {
    int b = blockIdx.x >> 7;
    int x = blockIdx.x & 127;
    __shared__ float zr[Hh];
    int t = threadIdx.x;  // 256
    if (t < Hh) zr[t] = z0[(b * Hh + t) * Xx + x];
    __syncthreads();
    int i = t >> 3, f = t & 7;
    const float* gw = Gw + (i * Ff + f) * Hh;
    float acc = 0.0f;
#pragma unroll
    for (int h = 0; h < Hh; h++) acc += gw[h] * zr[h];
    g_Gu[blockIdx.x * 256 + t] = acc;
}

// ---------------- K2: dHu[b,i,x,t] = sum_f Gu[b,x,i,f]*(xi[t+1]-xi[t]) ----------------
// (the A/Fu term is constant in t and cancels in the Euler increments)
__global__ void k2_dhu(const float* __restrict__ xi) {
    int b = blockIdx.x >> 7, x = blockIdx.x & 127;
    __shared__ float xs[Ff][Tt];
    __shared__ float gsh[256];
    int t = threadIdx.x;  // 256
#pragma unroll
    for (int f = 0; f < Ff; f++) xs[f][t] = xi[((b * Ff + f) * Xx + x) * Tt + t];
    gsh[t] = g_Gu[blockIdx.x * 256 + t];
    __syncthreads();
    if (t < Tm1) {
        float d[Ff];
#pragma unroll
        for (int f = 0; f < Ff; f++) d[f] = xs[f][t + 1] - xs[f][t];
        for (int i = 0; i < Hh; i++) {
            float acc = 0.0f;
#pragma unroll
            for (int f = 0; f < Ff; f++) acc += gsh[i * 8 + f] * d[f];
            g_dHu[((b * Hh + i) * Xx + x) * Tm1 + t] = acc;
        }
    }
}

// ---------------- K3b: z0ft[k,b,i] = sum_x S[k,x]*z0[b,i,x] ----------------
__global__ void k3b_z0ft(const float* __restrict__ z0) {
    int b = blockIdx.x >> 5, i = blockIdx.x & 31;  // 256 blocks
    __shared__ float row[Xx];
    int k = threadIdx.x;  // 128
    row[k] = z0[(b * Hh + i) * Xx + k];
    __syncthreads();
    float ar = 0.0f, ai = 0.0f;
    for (int x = 0; x < Xx; x++) {
        float2 s = g_Sfwd[x * Xx + k];
        float h = row[x];
        ar += s.x * h;
        ai += s.y * h;
    }
    g_z0ft[(k * Bb + b) * Hh + i] = make_float2(ar, ai);
}

// ---------------- K3: dXft[k,b,t,i] = sum_x S[k,x]*dHu[b,i,x,t] ----------------
__global__ void k3_dft() {
    int bid = blockIdx.x;       // 1024 = 256 (b,i) * 4 chunks
    int chunk = bid & 3;
    int bi = bid >> 2;
    int b = bi >> 5, i = bi & 31;
    int tc = chunk * 64;
    __shared__ __align__(16) float tile[Xx][64];
    const float* src = g_dHu + (size_t)bi * Xx * Tm1;
    int tid = threadIdx.x;  // 256
    for (int e = tid; e < Xx * 64; e += 256) {
        int x = e >> 6, ttl = e & 63;
        int t = tc + ttl;
        tile[x][ttl] = (t < Tm1) ? src[x * Tm1 + t] : 0.0f;
    }
    __syncthreads();
    int k = tid & 127, th = tid >> 7;
    float ar[32], ai[32];
#pragma unroll
    for (int q = 0; q < 32; q++) { ar[q] = 0.0f; ai[q] = 0.0f; }
    for (int x = 0; x < Xx; x++) {
        float2 s = g_Sfwd[x * Xx + k];
        const float4* hp = (const float4*)&tile[x][th * 32];
#pragma unroll
        for (int q4 = 0; q4 < 8; q4++) {
            float4 h = hp[q4];
            ar[q4 * 4 + 0] += s.x * h.x;  ai[q4 * 4 + 0] += s.y * h.x;
            ar[q4 * 4 + 1] += s.x * h.y;  ai[q4 * 4 + 1] += s.y * h.y;
            ar[q4 * 4 + 2] += s.x * h.z;  ai[q4 * 4 + 2] += s.y * h.z;
            ar[q4 * 4 + 3] += s.x * h.w;  ai[q4 * 4 + 3] += s.y * h.w;
        }
    }
#pragma unroll
    for (int q = 0; q < 32; q++) {
        int t = tc + th * 32 + q;
        if (t < Tm1) g_dXft[((k * Bb + b) * Tm1 + t) * Hh + i] = make_float2(ar[q], ai[q]);
    }
}

// ---------------- K4: the sequential CDE scan (dominant kernel) ----------------
// One block per Fourier mode x (128 blocks, 1024 threads). Thread (i,c) owns
// W[x,i,c,:]; j=0..7 in registers, j=8..31 in SMEM ([j][i][c] layout).
// State z in SMEM SoA (zr[ii][b], b contiguous -> broadcast LDS.128 quads).
// Complex MACs via packed fma.rn.f32x2 over b-pairs (2 FFMA2 per complex MAC).
// Epilogue: per-b butterfly reduce over lanes, lane c==b stages the increment
// to SMEM, then 256 threads apply the z update in parallel (no register
// arrays live across the reduction -> fits 64 regs @ 1024 thr without spills).
#define JR 8
#define JS 24
__global__ void __launch_bounds__(1024, 1)
k4_scan(const float* __restrict__ Wr, const float* __restrict__ Wi) {
    extern __shared__ float sm[];
    float2* Wsh   = (float2*)sm;               // [JS][32][32] (wr, wi)
    float* zr_sh  = (float*)(Wsh + JS * 1024); // [32][8]   index ii*8+b
    float* zi_sh  = zr_sh + 256;               // [32][8]
    float* dxr_sh = zi_sh + 256;               // [8][32]   index b*32+c
    float* dxi_sh = dxr_sh + 256;              // [8][32]
    float* str_sh = dxi_sh + 256;              // [32][8]   index i*8+b
    float* sti_sh = str_sh + 256;              // [32][8]
    int x = blockIdx.x;
    int tid = threadIdx.x;
    int i = tid >> 5, c = tid & 31;

    const float* wr = Wr + (((size_t)x * Hh + i) * Hh + c) * Hh;
    const float* wi = Wi + (((size_t)x * Hh + i) * Hh + c) * Hh;
    float wre[JR], wim[JR];
#pragma unroll
    for (int j = 0; j < JR; j++) { wre[j] = wr[j]; wim[j] = wi[j]; }
#pragma unroll
    for (int j = 0; j < JS; j++)
        Wsh[j * 1024 + tid] = make_float2(wr[JR + j], wi[JR + j]);

    if (tid < Bb * Hh) {
        int b = tid >> 5, ii = tid & 31;
        float2 z = g_z0ft[(x * Bb + b) * Hh + ii];
        zr_sh[ii * Bb + b] = z.x;
        zi_sh[ii * Bb + b] = z.y;
        g_Zall[((size_t)(x * Bb + b) * Tt + 0) * Hh + ii] = z;
    }

    const float2* dxbase = g_dXft + (size_t)(x * Bb) * Tm1 * Hh;
    float2 dnext = make_float2(0.0f, 0.0f);
    int ldb = tid >> 5, ldi = tid & 31;
    if (tid < Bb * Hh)
        dnext = dxbase[(size_t)ldb * Tm1 * Hh + ldi];  // t = 0
    __syncthreads();

    for (int t = 0; t < Tm1; t++) {
        if (tid < Bb * Hh) {
            dxr_sh[tid] = dnext.x;   // [b][c] layout
            dxi_sh[tid] = dnext.y;
        }
        __syncthreads();   // (A) orders z updates + dx stage vs this step's reads
        // prefetch next step's dx while we compute
        if (tid < Bb * Hh && t + 1 < Tm1)
            dnext = dxbase[((size_t)ldb * Tm1 + (t + 1)) * Hh + ldi];

        // packed accumulators: arp[p] = (ar[2p], ar[2p+1]) etc.
        unsigned long long arp[4], aip[4];
#pragma unroll
        for (int p = 0; p < 4; p++) { arp[p] = 0ULL; aip[p] = 0ULL; }

#pragma unroll
        for (int j = 0; j < JR; j++) {
            unsigned long long wrr = pk2(wre[j], wre[j]);
            unsigned long long wii = pk2(wim[j], wim[j]);
            unsigned long long wnn = pk2(-wim[j], -wim[j]);
            ulonglong2 zra = *(const ulonglong2*)&zr_sh[j * Bb];      // b0..3
            ulonglong2 zrb = *(const ulonglong2*)&zr_sh[j * Bb + 4];  // b4..7
            ulonglong2 zia = *(const ulonglong2*)&zi_sh[j * Bb];
            ulonglong2 zib = *(const ulonglong2*)&zi_sh[j * Bb + 4];
            arp[0] = fma2(wrr, zra.x, arp[0]); arp[0] = fma2(wnn, zia.x, arp[0]);
            aip[0] = fma2(wrr, zia.x, aip[0]); aip[0] = fma2(wii, zra.x, aip[0]);
            arp[1] = fma2(wrr, zra.y, arp[1]); arp[1] = fma2(wnn, zia.y, arp[1]);
            aip[1] = fma2(wrr, zia.y, aip[1]); aip[1] = fma2(wii, zra.y, aip[1]);
            arp[2] = fma2(wrr, zrb.x, arp[2]); arp[2] = fma2(wnn, zib.x, arp[2]);
            aip[2] = fma2(wrr, zib.x, aip[2]); aip[2] = fma2(wii, zrb.x, aip[2]);
            arp[3] = fma2(wrr, zrb.y, arp[3]); arp[3] = fma2(wnn, zib.y, arp[3]);
            aip[3] = fma2(wrr, zib.y, aip[3]); aip[3] = fma2(wii, zrb.y, aip[3]);
        }
#pragma unroll 6
        for (int j = 0; j < JS; j++) {
            float2 w = Wsh[j * 1024 + tid];
            unsigned long long wrr = pk2(w.x, w.x);
            unsigned long long wii = pk2(w.y, w.y);
            unsigned long long wnn = pk2(-w.y, -w.y);
            int jz = JR + j;
            ulonglong2 zra = *(const ulonglong2*)&zr_sh[jz * Bb];
            ulonglong2 zrb = *(const ulonglong2*)&zr_sh[jz * Bb + 4];
            ulonglong2 zia = *(const ulonglong2*)&zi_sh[jz * Bb];
            ulonglong2 zib = *(const ulonglong2*)&zi_sh[jz * Bb + 4];
            arp[0] = fma2(wrr, zra.x, arp[0]); arp[0] = fma2(wnn, zia.x, arp[0]);
            aip[0] = fma2(wrr, zia.x, aip[0]); aip[0] = fma2(wii, zra.x, aip[0]);
            arp[1] = fma2(wrr, zra.y, arp[1]); arp[1] = fma2(wnn, zia.y, arp[1]);
            aip[1] = fma2(wrr, zia.y, aip[1]); aip[1] = fma2(wii, zra.y, aip[1]);
            arp[2] = fma2(wrr, zrb.x, arp[2]); arp[2] = fma2(wnn, zib.x, arp[2]);
            aip[2] = fma2(wrr, zib.x, aip[2]); aip[2] = fma2(wii, zrb.x, aip[2]);
            arp[3] = fma2(wrr, zrb.y, arp[3]); arp[3] = fma2(wnn, zib.y, arp[3]);
            aip[3] = fma2(wrr, zib.y, aip[3]); aip[3] = fma2(wii, zrb.y, aip[3]);
        }

        // per-b: unpack in place, fz*dx, butterfly-reduce over c, stage to SMEM.
#pragma unroll
        for (int p = 0; p < 4; p++) {
            float a0, a1, q0, q1;
            upk2(arp[p], a0, a1);
            upk2(aip[p], q0, q1);
            {
                int b = 2 * p;
                float dxr = dxr_sh[b * Hh + c];
                float dxi = dxi_sh[b * Hh + c];
                float pr = a0 * dxr - q0 * dxi;
                float pi = a0 * dxi + q0 * dxr;
#pragma unroll
                for (int off = 16; off > 0; off >>= 1) {
                    pr += __shfl_xor_sync(0xffffffffu, pr, off);
                    pi += __shfl_xor_sync(0xffffffffu, pi, off);
                }
                if (c == b) { str_sh[i * Bb + b] = pr; sti_sh[i * Bb + b] = pi; }
            }
            {
                int b = 2 * p + 1;
                float dxr = dxr_sh[b * Hh + c];
                float dxi = dxi_sh[b * Hh + c];
                float pr = a1 * dxr - q1 * dxi;
                float pi = a1 * dxi + q1 * dxr;
#pragma unroll
                for (int off = 16; off > 0; off >>= 1) {
                    pr += __shfl_xor_sync(0xffffffffu, pr, off);
                    pi += __shfl_xor_sync(0xffffffffu, pi, off);
                }
                if (c == b) { str_sh[i * Bb + b] = pr; sti_sh[i * Bb + b] = pi; }
            }
        }
        __syncthreads();   // (B) all z/dx reads + stage writes done
        if (tid < Bb * Hh) {
            int b = tid >> 5, ii = tid & 31;
            float zx = zr_sh[ii * Bb + b] + str_sh[ii * Bb + b];
            float zy = zi_sh[ii * Bb + b] + sti_sh[ii * Bb + b];
            zr_sh[ii * Bb + b] = zx;
            zi_sh[ii * Bb + b] = zy;
            g_Zall[((size_t)(x * Bb + b) * Tt + (t + 1)) * Hh + ii] =
                make_float2(zx, zy);
        }
        // next iteration's sync (A) orders these writes vs. next step's reads
    }
}

// ---------------- K5: real inverse DFT to output (b,i,x,t) ----------------
__global__ void k5_idft(float* __restrict__ out) {
    int bid = blockIdx.x;         // 2048 = 256 (b,i) * 8 chunks of 32 t
    int chunk = bid & 7, bi = bid >> 3;
    int b = bi >> 5, i = bi & 31;
    int tc = chunk * 32;
    __shared__ __align__(16) float2 Zsh[Xx][32];
    int tid = threadIdx.x;  // 256
    for (int e = tid; e < Xx * 32; e += 256) {
        int k = e >> 5, ttl = e & 31;
        Zsh[k][ttl] = g_Zall[((size_t)(k * Bb + b) * Tt + tc + ttl) * Hh + i];
    }
    __syncthreads();
    int xx = tid & 127, th = tid >> 7;
    float acc[16];
#pragma unroll
    for (int q = 0; q < 16; q++) acc[q] = 0.0f;
    for (int k = 0; k < Xx; k++) {
        float2 cf = g_Sinv[k * Xx + xx];
        const float4* zp = (const float4*)&Zsh[k][th * 16];
#pragma unroll
        for (int q2 = 0; q2 < 8; q2++) {
            float4 z2 = zp[q2];  // (zr0, zi0, zr1, zi1)
            acc[q2 * 2 + 0] += cf.x * z2.x + cf.y * z2.y;
            acc[q2 * 2 + 1] += cf.x * z2.z + cf.y * z2.w;
        }
    }
    float* dst = out + ((size_t)bi * Xx + xx) * Tt + tc + th * 16;
#pragma unroll
    for (int q4 = 0; q4 < 4; q4++) {
        ((float4*)dst)[q4] = make_float4(acc[q4 * 4 + 0], acc[q4 * 4 + 1],
                                         acc[q4 * 4 + 2], acc[q4 * 4 + 3]);
    }
}

// ---------------- launch ----------------
extern "C" void kernel_launch(void* const* d_in, const int* in_sizes, int n_in,
                              void* d_out, int out_size) {
    const float* z0 = (const float*)d_in[0];
    const float* xi = (const float*)d_in[1];
    // d_in[2] = A : provably unused (constant-in-t term cancels in dX)
    const float* Gw = (const float*)d_in[3];
    const float* Wr = (const float*)d_in[4];
    const float* Wi = (const float*)d_in[5];

    k0_tables<<<64, 256>>>();
    k1_gu<<<Bb * Xx, 256>>>(z0, Gw);
    k2_dhu<<<Bb * Xx, 256>>>(xi);
    k3b_z0ft<<<Bb * Hh, 128>>>(z0);
    k3_dft<<<Bb * Hh * 4, 256>>>();

    // Wsh (JS*1024 float2) + 6 * 256-float staging/state arrays
    const int k4_smem = JS * 1024 * 8 + 6 * 256 * 4;  // 202752 bytes
    cudaFuncSetAttribute(k4_scan, cudaFuncAttributeMaxDynamicSharedMemorySize, k4_smem);
    k4_scan<<<Xx, 1024, k4_smem>>>(Wr, Wi);

    k5_idft<<<Bb * Hh * 8, 256>>>((float*)d_out);
}